// round 6
// baseline (speedup 1.0000x reference)
#include <cuda_runtime.h>
#include <cuda_bf16.h>
#include <cstdint>

// ============================================================================
// Problem constants (PoincareHead: B=8192, C=4096, D=512)
// ============================================================================
#define DIM 512
#define MAXB 8192
#define MAXC 4096

// Scratch (allowed: __device__ globals)
__device__ __nv_bfloat16 g_xh_bf[(size_t)MAXB * DIM];
__device__ __nv_bfloat16 g_cen_bf[(size_t)MAXC * DIM];
__device__ float g_x2[MAXB];
__device__ float g_y2[MAXC];

// ============================================================================
// PTX helpers — ONLY plain-compute_100-legal instructions
// (cp.async: sm_80; ldmatrix: sm_75; mma.sync bf16: sm_80)
// ============================================================================
__device__ __forceinline__ uint32_t smem_to_u32(const void* smem_ptr) {
    uint32_t addr;
    asm("{ .reg .u64 tmp; cvta.to.shared.u64 tmp, %1; cvt.u32.u64 %0, tmp; }"
        : "=r"(addr) : "l"(smem_ptr));
    return addr;
}

#define CP_ASYNC16(dst_u32, src_ptr) \
    asm volatile("cp.async.cg.shared.global [%0], [%1], 16;" \
                 :: "r"(dst_u32), "l"(src_ptr) : "memory")
#define CP_COMMIT()  asm volatile("cp.async.commit_group;" ::: "memory")
#define CP_WAIT_2()  asm volatile("cp.async.wait_group 2;" ::: "memory")
#define CP_WAIT_1()  asm volatile("cp.async.wait_group 1;" ::: "memory")
#define CP_WAIT_0()  asm volatile("cp.async.wait_group 0;" ::: "memory")

__device__ __forceinline__ void ldsm_x4(uint32_t* r, uint32_t addr) {
    asm volatile("ldmatrix.sync.aligned.m8n8.x4.shared.b16 {%0,%1,%2,%3}, [%4];"
        : "=r"(r[0]), "=r"(r[1]), "=r"(r[2]), "=r"(r[3]) : "r"(addr));
}

__device__ __forceinline__ void mma16816(float* c, const uint32_t* a, const uint32_t* b) {
    asm volatile(
        "mma.sync.aligned.m16n8k16.row.col.f32.bf16.bf16.f32 "
        "{%0,%1,%2,%3}, {%4,%5,%6,%7}, {%8,%9}, {%0,%1,%2,%3};"
        : "+f"(c[0]), "+f"(c[1]), "+f"(c[2]), "+f"(c[3])
        : "r"(a[0]), "r"(a[1]), "r"(a[2]), "r"(a[3]), "r"(b[0]), "r"(b[1]));
}

__device__ __forceinline__ uint32_t sw128(uint32_t off) {
    return off ^ ((off >> 3) & 0x70u);
}

// ============================================================================
// Prep kernels
// ============================================================================
__device__ __forceinline__ float block_sum_128(float v, float* sred) {
    #pragma unroll
    for (int o = 16; o > 0; o >>= 1)
        v += __shfl_xor_sync(0xffffffffu, v, o);
    __syncthreads();            // protect sred reuse from previous call
    if ((threadIdx.x & 31) == 0) sred[threadIdx.x >> 5] = v;
    __syncthreads();
    return sred[0] + sred[1] + sred[2] + sred[3];
}

// expmap0 + clip_to_ball for euclidean_emb rows
__global__ void __launch_bounds__(128)
prep_x_kernel(const float* __restrict__ emb, const float* __restrict__ logc,
              float* __restrict__ xh_out)
{
    __shared__ float sred[4];
    const int row = blockIdx.x;
    const int t = threadIdx.x;
    const float4 e = reinterpret_cast<const float4*>(emb + (size_t)row * DIM)[t];

    float ss = e.x * e.x + e.y * e.y + e.z * e.z + e.w * e.w;
    ss = block_sum_128(ss, sred);

    const float c = expf(logc[0]);
    const float sc = sqrtf(c);
    const float vn = fmaxf(sqrtf(ss), 1e-6f);
    const float tt = sc * vn;
    const float coeff = tanhf(tt) / tt;

    float4 y;
    y.x = coeff * e.x; y.y = coeff * e.y; y.z = coeff * e.z; y.w = coeff * e.w;
    float s2 = y.x * y.x + y.y * y.y + y.z * y.z + y.w * y.w;
    s2 = block_sum_128(s2, sred);

    const float MAX_NORM = (float)(1.0 - 1e-3);
    const float ny = fmaxf(sqrtf(s2), 1e-6f);
    const float factor = fminf(MAX_NORM / ny, 1.0f);

    float4 xh;
    xh.x = y.x * factor; xh.y = y.y * factor; xh.z = y.z * factor; xh.w = y.w * factor;

    reinterpret_cast<float4*>(xh_out + (size_t)row * DIM)[t] = xh;

    __nv_bfloat162* bp = reinterpret_cast<__nv_bfloat162*>(g_xh_bf + (size_t)row * DIM);
    bp[t * 2]     = __floats2bfloat162_rn(xh.x, xh.y);
    bp[t * 2 + 1] = __floats2bfloat162_rn(xh.z, xh.w);

    float x2 = xh.x * xh.x + xh.y * xh.y + xh.z * xh.z + xh.w * xh.w;
    x2 = block_sum_128(x2, sred);
    if (t == 0) g_x2[row] = x2;
}

// clip_to_ball for centroids rows
__global__ void __launch_bounds__(128)
prep_cen_kernel(const float* __restrict__ cen, float* __restrict__ ch_out)
{
    __shared__ float sred[4];
    const int row = blockIdx.x;
    const int t = threadIdx.x;
    const float4 e = reinterpret_cast<const float4*>(cen + (size_t)row * DIM)[t];

    float ss = e.x * e.x + e.y * e.y + e.z * e.z + e.w * e.w;
    ss = block_sum_128(ss, sred);

    const float MAX_NORM = (float)(1.0 - 1e-3);
    const float nn = fmaxf(sqrtf(ss), 1e-6f);
    const float factor = fminf(MAX_NORM / nn, 1.0f);

    float4 ch;
    ch.x = e.x * factor; ch.y = e.y * factor; ch.z = e.z * factor; ch.w = e.w * factor;

    reinterpret_cast<float4*>(ch_out + (size_t)row * DIM)[t] = ch;

    __nv_bfloat162* bp = reinterpret_cast<__nv_bfloat162*>(g_cen_bf + (size_t)row * DIM);
    bp[t * 2]     = __floats2bfloat162_rn(ch.x, ch.y);
    bp[t * 2 + 1] = __floats2bfloat162_rn(ch.z, ch.w);

    float y2 = ch.x * ch.x + ch.y * ch.y + ch.z * ch.z + ch.w * ch.w;
    y2 = block_sum_128(y2, sred);
    if (t == 0) g_y2[row] = y2;
}

// ============================================================================
// GEMM + arccosh epilogue: dists[B,C] from x_h @ cen_h^T
// mma.sync (HMMA) path — the only tensor path legal under .target sm_100.
// Tile: BM=128, BN=128, BK=64 (8 K-chunks). 256 threads = 8 warps in 2x4;
// each warp computes 64x32 with m16n8k16 bf16 MMA, fp32 register accum.
// 3-stage cp.async pipeline, SW128-swizzled smem, ldmatrix fragment loads.
// ============================================================================
static constexpr int STAGES = 3;
static constexpr int CHUNKS = 8;                 // 512 / 64
static constexpr uint32_t STAGE_BYTES = 32768;   // A 16KB + B 16KB
static constexpr uint32_t CTRL_BYTES = 2048;     // s_x2/s_dx/s_y2/s_dy
static constexpr size_t GEMM_DSMEM = 1024 /*align slack*/ + CTRL_BYTES + STAGES * STAGE_BYTES;

__device__ __forceinline__ void load_stage(uint32_t sb, int m0, int n0, int sl)
{
    const int tid = threadIdx.x;
    const uint32_t ab = sb + CTRL_BYTES + (uint32_t)(sl % STAGES) * STAGE_BYTES;
    const uint32_t bb = ab + 16384u;
    const __nv_bfloat16* agp = g_xh_bf  + ((size_t)m0 * DIM + sl * 64);
    const __nv_bfloat16* bgp = g_cen_bf + ((size_t)n0 * DIM + sl * 64);
    // A tile: 128 rows x 64 bf16 (128B/row) = 1024 x 16B transfers, 4 iters @256thr
    #pragma unroll
    for (int it = 0; it < 4; ++it) {
        int i = tid + it * 256;
        int r = i >> 3, seg = i & 7;
        uint32_t sa = ab + sw128((uint32_t)(r * 128 + seg * 16));
        CP_ASYNC16(sa, agp + (size_t)r * DIM + seg * 8);
    }
    #pragma unroll
    for (int it = 0; it < 4; ++it) {
        int i = tid + it * 256;
        int r = i >> 3, seg = i & 7;
        uint32_t sa = bb + sw128((uint32_t)(r * 128 + seg * 16));
        CP_ASYNC16(sa, bgp + (size_t)r * DIM + seg * 8);
    }
}

__global__ void __launch_bounds__(256)
poincare_gemm_kernel(const float* __restrict__ logc, float* __restrict__ dout, int Csz)
{
    extern __shared__ char dsm[];
    const uint32_t raw = smem_to_u32(dsm);
    const uint32_t sb = (raw + 1023u) & ~1023u;      // 1024-aligned base
    char* sbp = dsm + (sb - raw);
    float* s_x2 = (float*)(sbp);          // 128 floats
    float* s_dx = (float*)(sbp + 512);    // 128 floats
    float* s_y2 = (float*)(sbp + 1024);   // 128 floats
    float* s_dy = (float*)(sbp + 1536);   // 128 floats

    const int tid  = threadIdx.x;
    const int wid  = tid >> 5;
    const int lane = tid & 31;
    const int wm = wid >> 2;      // 0..1  -> 64 rows each
    const int wn = wid & 3;       // 0..3  -> 32 cols each
    const int n0 = blockIdx.x * 128;
    const int m0 = blockIdx.y * 128;

    const float c = expf(logc[0]);
    const float MN2 = (float)((1.0 - 1e-3) * (1.0 - 1e-3));

    // Per-row / per-col terms into smem
    if (tid < 128) {
        float x2v = g_x2[m0 + tid];
        s_x2[tid] = x2v;
        s_dx[tid] = 1.0f - c * fminf(x2v, MN2);
    } else {
        int j = tid - 128;
        float y2v = g_y2[n0 + j];
        s_y2[j] = y2v;
        s_dy[j] = 1.0f - c * fminf(y2v, MN2);
    }

    // Prologue: fill all 3 stages
    #pragma unroll
    for (int sl = 0; sl < STAGES; ++sl) { load_stage(sb, m0, n0, sl); CP_COMMIT(); }

    // Accumulators: warp tile 64x32 -> 4 mf x 4 nf x 4 regs
    float acc[4][4][4];
    #pragma unroll
    for (int mf = 0; mf < 4; ++mf)
        #pragma unroll
        for (int nf = 0; nf < 4; ++nf)
            #pragma unroll
            for (int i = 0; i < 4; ++i) acc[mf][nf][i] = 0.0f;

    const int lr = lane & 15;            // row within 16-row ldmatrix tile
    const int lk = (lane >> 4) * 16;     // byte offset of k-half (0 or 16)

    for (int s = 0; s < CHUNKS; ++s) {
        if (s < CHUNKS - 2)       CP_WAIT_2();
        else if (s == CHUNKS - 2) CP_WAIT_1();
        else                      CP_WAIT_0();
        __syncthreads();   // stage s visible to all warps

        const uint32_t ab = sb + CTRL_BYTES + (uint32_t)(s % STAGES) * STAGE_BYTES;
        const uint32_t bb = ab + 16384u;

        #pragma unroll
        for (int ks = 0; ks < 4; ++ks) {
            uint32_t af[4][4];
            #pragma unroll
            for (int mf = 0; mf < 4; ++mf)
                ldsm_x4(af[mf],
                        ab + sw128((uint32_t)((wm * 64 + mf * 16 + lr) * 128 + ks * 32 + lk)));
            uint32_t bf[4][2];
            #pragma unroll
            for (int np = 0; np < 2; ++np) {
                uint32_t t[4];
                ldsm_x4(t,
                        bb + sw128((uint32_t)((wn * 32 + np * 16 + lr) * 128 + ks * 32 + lk)));
                bf[2 * np][0] = t[0]; bf[2 * np + 1][0] = t[1];
                bf[2 * np][1] = t[2]; bf[2 * np + 1][1] = t[3];
            }
            #pragma unroll
            for (int mf = 0; mf < 4; ++mf)
                #pragma unroll
                for (int nf = 0; nf < 4; ++nf)
                    mma16816(acc[mf][nf], af[mf], bf[nf]);
        }

        __syncthreads();   // all warps done reading buffer (s % STAGES)
        if (s + STAGES < CHUNKS) {
            load_stage(sb, m0, n0, s + STAGES);
            CP_COMMIT();
        }
    }

    // ------------------------------------------------------------------
    // Epilogue: Poincare distance, fused, straight from register accum.
    // mma frag layout: reg i in acc[mf][nf]:
    //   i0:(row g,     col 2q)   i1:(row g,     col 2q+1)
    //   i2:(row g+8,   col 2q)   i3:(row g+8,   col 2q+1)
    // with g = lane>>2, q = lane&3.
    // ------------------------------------------------------------------
    const float inv_sc = rsqrtf(c);
    const float two_c  = 2.0f * c;
    const int g = lane >> 2;
    const int q = lane & 3;

    #pragma unroll
    for (int mf = 0; mf < 4; ++mf) {
        const int r0 = wm * 64 + mf * 16 + g;    // local row (and r0+8)
        const float x2a = s_x2[r0],     dxa = s_dx[r0];
        const float x2b = s_x2[r0 + 8], dxb = s_dx[r0 + 8];
        float* out0 = dout + (size_t)(m0 + r0)     * (size_t)Csz + n0;
        float* out1 = dout + (size_t)(m0 + r0 + 8) * (size_t)Csz + n0;
        #pragma unroll
        for (int nf = 0; nf < 4; ++nf) {
            const int col = wn * 32 + nf * 8 + 2 * q;
            const float y20 = s_y2[col],     dy0 = s_dy[col];
            const float y21 = s_y2[col + 1], dy1 = s_dy[col + 1];

            float d00 = x2a + y20 - 2.0f * acc[mf][nf][0];
            float d01 = x2a + y21 - 2.0f * acc[mf][nf][1];
            float d10 = x2b + y20 - 2.0f * acc[mf][nf][2];
            float d11 = x2b + y21 - 2.0f * acc[mf][nf][3];

            float a00 = fmaxf(1.0f + __fdividef(two_c * d00, fmaxf(dxa * dy0, 1e-6f)), 1.0f + 1e-6f);
            float a01 = fmaxf(1.0f + __fdividef(two_c * d01, fmaxf(dxa * dy1, 1e-6f)), 1.0f + 1e-6f);
            float a10 = fmaxf(1.0f + __fdividef(two_c * d10, fmaxf(dxb * dy0, 1e-6f)), 1.0f + 1e-6f);
            float a11 = fmaxf(1.0f + __fdividef(two_c * d11, fmaxf(dxb * dy1, 1e-6f)), 1.0f + 1e-6f);

            float s00 = fmaf(a00, a00, -1.0f); s00 = s00 * __frsqrt_rn(s00);
            float s01 = fmaf(a01, a01, -1.0f); s01 = s01 * __frsqrt_rn(s01);
            float s10 = fmaf(a10, a10, -1.0f); s10 = s10 * __frsqrt_rn(s10);
            float s11 = fmaf(a11, a11, -1.0f); s11 = s11 * __frsqrt_rn(s11);

            float2 v0 = make_float2(__logf(a00 + s00) * inv_sc, __logf(a01 + s01) * inv_sc);
            float2 v1 = make_float2(__logf(a10 + s10) * inv_sc, __logf(a11 + s11) * inv_sc);

            *reinterpret_cast<float2*>(out0 + col) = v0;
            *reinterpret_cast<float2*>(out1 + col) = v1;
        }
    }
}

// ============================================================================
// Launch
// ============================================================================
extern "C" void kernel_launch(void* const* d_in, const int* in_sizes, int n_in,
                              void* d_out, int out_size)
{
    const float* emb  = (const float*)d_in[0];
    const float* logc = (const float*)d_in[1];
    const float* cen  = (const float*)d_in[2];
    float* out = (float*)d_out;

    const int B = in_sizes[0] / DIM;   // 8192
    const int C = in_sizes[2] / DIM;   // 4096

    float* out_dists = out;
    float* out_xh    = out + (size_t)B * C;
    float* out_ch    = out_xh + (size_t)B * DIM;

    prep_x_kernel<<<B, 128>>>(emb, logc, out_xh);
    prep_cen_kernel<<<C, 128>>>(cen, out_ch);

    cudaFuncSetAttribute(poincare_gemm_kernel,
                         cudaFuncAttributeMaxDynamicSharedMemorySize,
                         (int)GEMM_DSMEM);
    dim3 grid(C / 128, B / 128);
    poincare_gemm_kernel<<<grid, 256, GEMM_DSMEM>>>(logc, out_dists, C);
}